// round 1
// baseline (speedup 1.0000x reference)
#include <cuda_runtime.h>
#include <math.h>

#define N 8192
#define D 256
#define SPLITS 4
#define COLS_PER_SPLIT (N / SPLITS)   // 2048

#define BM 128
#define BN 128
#define BK 16
#define TM 8
#define TN 8

// Scratch (allocation-free rule: __device__ globals)
__device__ float g_fnorm[N * D];          // 8 MB normalized features
__device__ float g_partial[SPLITS * N];   // per-split exp-sums per row
__device__ float g_posdot[N];             // dot(f_i, f_pos(i))

// ---------------------------------------------------------------------------
// Kernel 1: row L2-normalize. One block per row, 256 threads (= D).
// ---------------------------------------------------------------------------
__global__ void normalize_kernel(const float* __restrict__ x) {
    int row = blockIdx.x;
    int t   = threadIdx.x;

    float v  = x[row * D + t];
    float ss = v * v;
    // warp reduce
    #pragma unroll
    for (int o = 16; o > 0; o >>= 1)
        ss += __shfl_xor_sync(0xffffffffu, ss, o);

    __shared__ float ws[8];
    __shared__ float s_rn;
    if ((t & 31) == 0) ws[t >> 5] = ss;
    __syncthreads();
    if (t < 32) {
        float s = (t < 8) ? ws[t] : 0.0f;
        #pragma unroll
        for (int o = 4; o > 0; o >>= 1)
            s += __shfl_xor_sync(0xffffffffu, s, o);
        if (t == 0) s_rn = 1.0f / fmaxf(sqrtf(s), 1e-8f);
    }
    __syncthreads();
    g_fnorm[row * D + t] = v * s_rn;
}

// ---------------------------------------------------------------------------
// Kernel 2: fused sim GEMM + exp + streaming row sum.
// grid = (64 row-blocks, 4 column-splits), 256 threads, 8x8 microtiles.
// For rows [i0, i0+128) x cols [sp*2048, sp*2048+2048):
//   rowsum_i += sum_j!=i exp(dot(f_i,f_j)/T);  posdot[i] = dot when j==pos(i)
// ---------------------------------------------------------------------------
__global__ __launch_bounds__(256, 2) void simlse_kernel() {
    const int rb  = blockIdx.x;          // 0..63
    const int sp  = blockIdx.y;          // 0..3
    const int i0  = rb * BM;
    const int tid = threadIdx.x;
    const int tx  = tid & 15;            // column group 0..15
    const int ty  = tid >> 4;            // row group 0..15

    __shared__ float As[BK][BM + 4];
    __shared__ float Bs[BK][BM + 4];

    const float invT = 1.0f / 0.07f;

    float rs[TM];
    #pragma unroll
    for (int ii = 0; ii < TM; ii++) rs[ii] = 0.0f;

    for (int jt = 0; jt < COLS_PER_SPLIT / BN; jt++) {   // 16 column tiles
        const int j0 = sp * COLS_PER_SPLIT + jt * BN;

        float acc[TM][TN];
        #pragma unroll
        for (int ii = 0; ii < TM; ii++)
            #pragma unroll
            for (int jj = 0; jj < TN; jj++) acc[ii][jj] = 0.0f;

        for (int k0 = 0; k0 < D; k0 += BK) {
            // Load 128x16 A-tile and B-tile (same matrix, different rows),
            // transposed into smem As[k][row]. 512 float4 per tile, 2/thread.
            #pragma unroll
            for (int q = 0; q < 2; q++) {
                int idx = tid * 2 + q;   // 0..511
                int r   = idx >> 2;      // row within tile 0..127
                int c4  = idx & 3;       // which float4 of the 16 k-columns

                float4 va = *(const float4*)&g_fnorm[(i0 + r) * D + k0 + c4 * 4];
                As[c4 * 4 + 0][r] = va.x;
                As[c4 * 4 + 1][r] = va.y;
                As[c4 * 4 + 2][r] = va.z;
                As[c4 * 4 + 3][r] = va.w;

                float4 vb = *(const float4*)&g_fnorm[(j0 + r) * D + k0 + c4 * 4];
                Bs[c4 * 4 + 0][r] = vb.x;
                Bs[c4 * 4 + 1][r] = vb.y;
                Bs[c4 * 4 + 2][r] = vb.z;
                Bs[c4 * 4 + 3][r] = vb.w;
            }
            __syncthreads();

            #pragma unroll
            for (int k = 0; k < BK; k++) {
                float a[TM], b[TN];
                #pragma unroll
                for (int ii = 0; ii < TM; ii++) a[ii] = As[k][ty * TM + ii];
                #pragma unroll
                for (int jj = 0; jj < TN; jj++) b[jj] = Bs[k][tx * TN + jj];
                #pragma unroll
                for (int ii = 0; ii < TM; ii++)
                    #pragma unroll
                    for (int jj = 0; jj < TN; jj++)
                        acc[ii][jj] = fmaf(a[ii], b[jj], acc[ii][jj]);
            }
            __syncthreads();
        }

        // Epilogue: exp + accumulate, skip diagonal, capture positive dot.
        #pragma unroll
        for (int ii = 0; ii < TM; ii++) {
            const int i  = i0 + ty * TM + ii;
            const int pc = (i + N / 2) & (N - 1);   // positive column of row i
            #pragma unroll
            for (int jj = 0; jj < TN; jj++) {
                const int j = j0 + tx * TN + jj;
                const float c = acc[ii][jj];
                if (j == pc) g_posdot[i] = c;
                if (j != i)  rs[ii] += __expf(c * invT);
            }
        }
    }

    // Reduce rs across the 16 lanes (same ty) sharing each row group.
    // tx == lane&15; xor-butterfly over offsets 1,2,4,8 stays in the group.
    #pragma unroll
    for (int ii = 0; ii < TM; ii++) {
        float v = rs[ii];
        #pragma unroll
        for (int o = 8; o > 0; o >>= 1)
            v += __shfl_xor_sync(0xffffffffu, v, o);
        if (tx == 0)
            g_partial[sp * N + i0 + ty * TM + ii] = v;
    }
}

// ---------------------------------------------------------------------------
// Kernel 3: nll_i = log(sum of split partials) - posdot[i]/T ; mean -> out[0]
// ---------------------------------------------------------------------------
__global__ void finalize_kernel(float* __restrict__ out) {
    const int t = threadIdx.x;   // 1024 threads
    const float invT = 1.0f / 0.07f;

    float local = 0.0f;
    for (int i = t; i < N; i += 1024) {
        float s = g_partial[i] + g_partial[N + i] +
                  g_partial[2 * N + i] + g_partial[3 * N + i];
        local += logf(s) - g_posdot[i] * invT;
    }

    // block reduce (1024 threads = 32 warps)
    #pragma unroll
    for (int o = 16; o > 0; o >>= 1)
        local += __shfl_xor_sync(0xffffffffu, local, o);

    __shared__ float ws[32];
    if ((t & 31) == 0) ws[t >> 5] = local;
    __syncthreads();
    if (t < 32) {
        float s = ws[t];
        #pragma unroll
        for (int o = 16; o > 0; o >>= 1)
            s += __shfl_xor_sync(0xffffffffu, s, o);
        if (t == 0) out[0] = s / (float)N;
    }
}

// ---------------------------------------------------------------------------
extern "C" void kernel_launch(void* const* d_in, const int* in_sizes, int n_in,
                              void* d_out, int out_size) {
    const float* features = (const float*)d_in[0];
    float* out = (float*)d_out;

    normalize_kernel<<<N, 256>>>(features);

    dim3 grid(N / BM, SPLITS);
    simlse_kernel<<<grid, 256>>>();

    finalize_kernel<<<1, 1024>>>(out);
}

// round 3
// speedup vs baseline: 8.6223x; 8.6223x over previous
#include <cuda_runtime.h>
#include <cuda_bf16.h>
#include <math.h>
#include <stdint.h>

#define N 8192
#define D 256
#define INVT (1.0f / 0.07f)

// CTA tile 128x128, K streamed in 4 chunks of 64. 256 threads = 8 warps (4 x 2).
// Warp tile 32x64: mma m16n8k16 -> mf 2 x nf 8, accum c[2][8][4].
#define KC 64
#define NSPLITS 128   // 64 cb * 2 wn

__device__ __align__(16) __nv_bfloat16 g_fbf16[N * D];   // 4MB normalized bf16
__device__ float g_partial[NSPLITS * N];                  // 4MB row exp-sum partials
__device__ float g_posdot[N];
__device__ float g_blk[32];

// ---------------------------------------------------------------------------
__device__ __forceinline__ uint32_t smem_u32(const void* p) {
    uint32_t a;
    asm("{ .reg .u64 t; cvta.to.shared.u64 t, %1; cvt.u32.u64 %0, t; }" : "=r"(a) : "l"(p));
    return a;
}
#define SW128(o) ((o) ^ (((o) >> 3) & 0x70))

__device__ __forceinline__ void cpasync16(uint32_t s, const void* g) {
    asm volatile("cp.async.cg.shared.global [%0], [%1], 16;" :: "r"(s), "l"(g));
}
#define CP_COMMIT() asm volatile("cp.async.commit_group;" ::: "memory")
#define CP_WAIT(n)  asm volatile("cp.async.wait_group %0;" :: "n"(n) : "memory")

__device__ __forceinline__ void ldsm_x4(uint32_t& r0, uint32_t& r1, uint32_t& r2,
                                        uint32_t& r3, uint32_t a) {
    asm volatile("ldmatrix.sync.aligned.m8n8.x4.shared.b16 {%0,%1,%2,%3}, [%4];"
        : "=r"(r0), "=r"(r1), "=r"(r2), "=r"(r3) : "r"(a));
}
__device__ __forceinline__ void mma16816(float* c, uint32_t a0, uint32_t a1,
                                         uint32_t a2, uint32_t a3,
                                         uint32_t b0, uint32_t b1) {
    asm volatile(
        "mma.sync.aligned.m16n8k16.row.col.f32.bf16.bf16.f32 "
        "{%0,%1,%2,%3},{%4,%5,%6,%7},{%8,%9},{%0,%1,%2,%3};"
        : "+f"(c[0]), "+f"(c[1]), "+f"(c[2]), "+f"(c[3])
        : "r"(a0), "r"(a1), "r"(a2), "r"(a3), "r"(b0), "r"(b1));
}

// ---------------------------------------------------------------------------
// Kernel 1: row L2-normalize -> bf16
// ---------------------------------------------------------------------------
__global__ void normalize_kernel(const float* __restrict__ x) {
    int row = blockIdx.x;
    int t   = threadIdx.x;

    float v  = x[row * D + t];
    float ss = v * v;
    #pragma unroll
    for (int o = 16; o > 0; o >>= 1) ss += __shfl_xor_sync(0xffffffffu, ss, o);

    __shared__ float ws[8];
    __shared__ float s_rn;
    if ((t & 31) == 0) ws[t >> 5] = ss;
    __syncthreads();
    if (t < 32) {
        float s = (t < 8) ? ws[t] : 0.0f;
        #pragma unroll
        for (int o = 4; o > 0; o >>= 1) s += __shfl_xor_sync(0xffffffffu, s, o);
        if (t == 0) s_rn = 1.0f / fmaxf(sqrtf(s), 1e-8f);
    }
    __syncthreads();
    g_fbf16[row * D + t] = __float2bfloat16(v * s_rn);
}

// ---------------------------------------------------------------------------
// Kernel 2: HMMA fused sim GEMM + exp + streaming row sums.
// grid (64 rb, 64 cb), 256 threads. smem: A/B double-buffered 64-K chunks.
// ---------------------------------------------------------------------------
__global__ __launch_bounds__(256, 2) void simlse_mma() {
    // smem: bufA[2] 16KB each, bufB[2] 16KB each = 64KB
    extern __shared__ __align__(1024) char smem[];
    const uint32_t sA0 = smem_u32(smem);
    const uint32_t sB0 = sA0 + 2 * 16384;

    const int tid  = threadIdx.x;
    const int wid  = tid >> 5;
    const int lane = tid & 31;
    const int wm   = wid >> 1;         // 0..3  (32-row slice)
    const int wn   = wid & 1;          // 0..1  (64-col slice)
    const int rb   = blockIdx.x;
    const int cb   = blockIdx.y;
    const int i0   = rb * 128;
    const int j0   = cb * 128;

    const int sel = lane >> 3;         // ldmatrix tile selector
    const int sub = lane & 7;
    const int g   = lane >> 2;         // mma row-in-group
    const int q   = lane & 3;          // mma col pair

    float c[2][8][4];
    #pragma unroll
    for (int mf = 0; mf < 2; mf++)
        #pragma unroll
        for (int nf = 0; nf < 8; nf++)
            #pragma unroll
            for (int e = 0; e < 4; e++) c[mf][nf][e] = 0.0f;

    // ---- chunk loader: 128 rows x 64 k bf16 (16KB) per matrix ----
    auto load_chunk = [&](int kc, int bf) {
        const __nv_bfloat16* gA = g_fbf16 + (size_t)i0 * D + kc * KC;
        const __nv_bfloat16* gB = g_fbf16 + (size_t)j0 * D + kc * KC;
        const uint32_t dA = sA0 + bf * 16384;
        const uint32_t dB = sB0 + bf * 16384;
        #pragma unroll
        for (int v = 0; v < 4; v++) {
            int idx = tid + 256 * v;       // 0..1023
            int r   = idx >> 3;            // 0..127
            int ci  = idx & 7;             // 16B unit
            uint32_t so = SW128(r * 128 + ci * 16);
            cpasync16(dA + so, gA + (size_t)r * D + ci * 8);
            cpasync16(dB + so, gB + (size_t)r * D + ci * 8);
        }
    };

    load_chunk(0, 0);
    CP_COMMIT();

    for (int kc = 0; kc < 4; kc++) {
        if (kc < 3) { load_chunk(kc + 1, (kc + 1) & 1); CP_COMMIT(); CP_WAIT(1); }
        else        { CP_WAIT(0); }
        __syncthreads();

        const uint32_t bA = sA0 + (kc & 1) * 16384;
        const uint32_t bB = sB0 + (kc & 1) * 16384;

        #pragma unroll
        for (int ks = 0; ks < 4; ks++) {
            // A fragments: mf in {0,1}
            uint32_t a[2][4];
            #pragma unroll
            for (int mf = 0; mf < 2; mf++) {
                int row = wm * 32 + mf * 16 + (sel & 1) * 8 + sub;
                uint32_t off = (uint32_t)(row * 128 + ks * 32 + (sel >> 1) * 16);
                ldsm_x4(a[mf][0], a[mf][1], a[mf][2], a[mf][3], bA + SW128(off));
            }
            // B fragments: 4 ldmatrix.x4 cover nf 0..7
            uint32_t b[8][2];
            #pragma unroll
            for (int p = 0; p < 4; p++) {
                int n = wn * 64 + p * 16 + (sel >> 1) * 8 + sub;
                uint32_t off = (uint32_t)(n * 128 + ks * 32 + (sel & 1) * 16);
                uint32_t r0, r1, r2, r3;
                ldsm_x4(r0, r1, r2, r3, bB + SW128(off));
                b[2 * p][0] = r0; b[2 * p][1] = r1;
                b[2 * p + 1][0] = r2; b[2 * p + 1][1] = r3;
            }
            #pragma unroll
            for (int mf = 0; mf < 2; mf++)
                #pragma unroll
                for (int nf = 0; nf < 8; nf++)
                    mma16816(c[mf][nf], a[mf][0], a[mf][1], a[mf][2], a[mf][3],
                             b[nf][0], b[nf][1]);
        }
        __syncthreads();
    }

    // ---- epilogue: exp + mask + positive capture + row sums ----
    float rs[2][2] = {{0.0f, 0.0f}, {0.0f, 0.0f}};

    #pragma unroll
    for (int mf = 0; mf < 2; mf++) {
        #pragma unroll
        for (int h = 0; h < 2; h++) {
            const int i  = i0 + wm * 32 + mf * 16 + 8 * h + g;
            const int pc = (i + N / 2) & (N - 1);
            float acc = 0.0f;
            #pragma unroll
            for (int nf = 0; nf < 8; nf++) {
                #pragma unroll
                for (int cc = 0; cc < 2; cc++) {
                    const int j = j0 + wn * 64 + nf * 8 + 2 * q + cc;
                    const float v = c[mf][nf][h * 2 + cc];
                    if (j == pc) g_posdot[i] = v;
                    if (j != i)  acc += __expf(v * INVT);
                }
            }
            rs[mf][h] = acc;
        }
    }

    // reduce across the 4 lanes (q) sharing each row, write partials
    #pragma unroll
    for (int mf = 0; mf < 2; mf++) {
        #pragma unroll
        for (int h = 0; h < 2; h++) {
            float v = rs[mf][h];
            v += __shfl_xor_sync(0xffffffffu, v, 1);
            v += __shfl_xor_sync(0xffffffffu, v, 2);
            if (q == 0) {
                const int i = i0 + wm * 32 + mf * 16 + 8 * h + g;
                g_partial[(cb * 2 + wn) * N + i] = v;
            }
        }
    }
}

// ---------------------------------------------------------------------------
// Kernel 3a: per-row nll, block partial sums. 32 blocks x 256 threads.
// ---------------------------------------------------------------------------
__global__ void finalize1_kernel() {
    const int i = blockIdx.x * 256 + threadIdx.x;   // 8192 threads cover rows
    float s = 0.0f;
    #pragma unroll 8
    for (int sp = 0; sp < NSPLITS; sp++) s += g_partial[sp * N + i];
    float local = logf(s) - g_posdot[i] * INVT;

    #pragma unroll
    for (int o = 16; o > 0; o >>= 1) local += __shfl_xor_sync(0xffffffffu, local, o);
    __shared__ float ws[8];
    if ((threadIdx.x & 31) == 0) ws[threadIdx.x >> 5] = local;
    __syncthreads();
    if (threadIdx.x < 32) {
        float v = (threadIdx.x < 8) ? ws[threadIdx.x] : 0.0f;
        #pragma unroll
        for (int o = 4; o > 0; o >>= 1) v += __shfl_xor_sync(0xffffffffu, v, o);
        if (threadIdx.x == 0) g_blk[blockIdx.x] = v;
    }
}

// Kernel 3b: deterministic final sum.
__global__ void finalize2_kernel(float* __restrict__ out) {
    float v = g_blk[threadIdx.x];   // 32 threads
    #pragma unroll
    for (int o = 16; o > 0; o >>= 1) v += __shfl_xor_sync(0xffffffffu, v, o);
    if (threadIdx.x == 0) out[0] = v / (float)N;
}

// ---------------------------------------------------------------------------
extern "C" void kernel_launch(void* const* d_in, const int* in_sizes, int n_in,
                              void* d_out, int out_size) {
    const float* features = (const float*)d_in[0];
    float* out = (float*)d_out;

    static bool attr_set = false;
    if (!attr_set) {
        cudaFuncSetAttribute(simlse_mma, cudaFuncAttributeMaxDynamicSharedMemorySize,
                             64 * 1024);
        attr_set = true;
    }

    normalize_kernel<<<N, 256>>>(features);
    simlse_mma<<<dim3(64, 64), 256, 64 * 1024>>>();
    finalize1_kernel<<<32, 256>>>();
    finalize2_kernel<<<1, 32>>>(out);
}

// round 4
// speedup vs baseline: 11.0945x; 1.2867x over previous
#include <cuda_runtime.h>
#include <cuda_bf16.h>
#include <math.h>
#include <stdint.h>

#define N 8192
#define D 256
#define INVT (1.0f / 0.07f)
#define KC 64
#define NB 64                 // 8192/128 blocks per dim
#define NTILE (NB * (NB + 1) / 2)   // 2080 upper-triangular tiles

__device__ __align__(16) __nv_bfloat16 g_fbf16[N * D];  // 4MB normalized bf16
__device__ float g_rowpart[2 * NB * N];   // [cb*2+wn][i]  4MB
__device__ float g_colpart[4 * NB * N];   // [rb*4+wm][j]  8MB
__device__ float g_posdot[N];
__device__ float g_blk[32];
__device__ unsigned int g_cnt;

// ---------------------------------------------------------------------------
__device__ __forceinline__ uint32_t smem_u32(const void* p) {
    uint32_t a;
    asm("{ .reg .u64 t; cvta.to.shared.u64 t, %1; cvt.u32.u64 %0, t; }" : "=r"(a) : "l"(p));
    return a;
}
#define SW128(o) ((o) ^ (((o) >> 3) & 0x70))

__device__ __forceinline__ void cpasync16(uint32_t s, const void* g) {
    asm volatile("cp.async.cg.shared.global [%0], [%1], 16;" :: "r"(s), "l"(g));
}
#define CP_COMMIT() asm volatile("cp.async.commit_group;" ::: "memory")
#define CP_WAIT(n)  asm volatile("cp.async.wait_group %0;" :: "n"(n) : "memory")

__device__ __forceinline__ void ldsm_x4(uint32_t& r0, uint32_t& r1, uint32_t& r2,
                                        uint32_t& r3, uint32_t a) {
    asm volatile("ldmatrix.sync.aligned.m8n8.x4.shared.b16 {%0,%1,%2,%3}, [%4];"
        : "=r"(r0), "=r"(r1), "=r"(r2), "=r"(r3) : "r"(a));
}
__device__ __forceinline__ void mma16816(float* c, uint32_t a0, uint32_t a1,
                                         uint32_t a2, uint32_t a3,
                                         uint32_t b0, uint32_t b1) {
    asm volatile(
        "mma.sync.aligned.m16n8k16.row.col.f32.bf16.bf16.f32 "
        "{%0,%1,%2,%3},{%4,%5,%6,%7},{%8,%9},{%0,%1,%2,%3};"
        : "+f"(c[0]), "+f"(c[1]), "+f"(c[2]), "+f"(c[3])
        : "r"(a0), "r"(a1), "r"(a2), "r"(a3), "r"(b0), "r"(b1));
}

// ---------------------------------------------------------------------------
// Kernel 1: row L2-normalize -> bf16. Warp per row, 8 rows/CTA.
// ---------------------------------------------------------------------------
__global__ void normalize_kernel(const float* __restrict__ x) {
    const int warp = threadIdx.x >> 5;
    const int lane = threadIdx.x & 31;
    const int row  = blockIdx.x * 8 + warp;

    const float* xr = x + (size_t)row * D + lane * 8;
    float4 v0 = *(const float4*)xr;
    float4 v1 = *(const float4*)(xr + 4);

    float ss = v0.x * v0.x + v0.y * v0.y + v0.z * v0.z + v0.w * v0.w +
               v1.x * v1.x + v1.y * v1.y + v1.z * v1.z + v1.w * v1.w;
    #pragma unroll
    for (int o = 16; o > 0; o >>= 1) ss += __shfl_xor_sync(0xffffffffu, ss, o);

    const float rn = 1.0f / fmaxf(sqrtf(ss), 1e-8f);

    __nv_bfloat162 p[4];
    p[0] = __floats2bfloat162_rn(v0.x * rn, v0.y * rn);
    p[1] = __floats2bfloat162_rn(v0.z * rn, v0.w * rn);
    p[2] = __floats2bfloat162_rn(v1.x * rn, v1.y * rn);
    p[3] = __floats2bfloat162_rn(v1.z * rn, v1.w * rn);
    *(uint4*)(g_fbf16 + (size_t)row * D + lane * 8) = *(uint4*)p;
}

// ---------------------------------------------------------------------------
// Kernel 2: HMMA fused sim GEMM, upper-triangular tiles only.
// Each off-diag tile contributes row-sums for its i-range AND col-sums
// (= row-sums of the j-range by symmetry) from the same exp values.
// ---------------------------------------------------------------------------
__global__ __launch_bounds__(256, 2) void simlse_mma() {
    extern __shared__ __align__(1024) char smem[];
    const uint32_t sA0 = smem_u32(smem);
    const uint32_t sB0 = sA0 + 2 * 16384;

    // triangular tile map: tile t -> (rb, cb), cb >= rb
    int t = blockIdx.x, rb = 0, base = 0;
    while (base + (NB - rb) <= t) { base += NB - rb; rb++; }
    const int cb = rb + (t - base);
    const bool diag = (rb == cb);

    const int tid  = threadIdx.x;
    const int wid  = tid >> 5;
    const int lane = tid & 31;
    const int wm   = wid >> 1;         // 0..3  (32-row slice)
    const int wn   = wid & 1;          // 0..1  (64-col slice)
    const int i0   = rb * 128;
    const int j0   = cb * 128;

    const int sel = lane >> 3;
    const int sub = lane & 7;
    const int g   = lane >> 2;
    const int q   = lane & 3;

    float c[2][8][4];
    #pragma unroll
    for (int mf = 0; mf < 2; mf++)
        #pragma unroll
        for (int nf = 0; nf < 8; nf++)
            #pragma unroll
            for (int e = 0; e < 4; e++) c[mf][nf][e] = 0.0f;

    auto load_chunk = [&](int kc, int bf) {
        const __nv_bfloat16* gA = g_fbf16 + (size_t)i0 * D + kc * KC;
        const __nv_bfloat16* gB = g_fbf16 + (size_t)j0 * D + kc * KC;
        const uint32_t dA = sA0 + bf * 16384;
        const uint32_t dB = sB0 + bf * 16384;
        #pragma unroll
        for (int v = 0; v < 4; v++) {
            int idx = tid + 256 * v;
            int r   = idx >> 3;
            int ci  = idx & 7;
            uint32_t so = SW128(r * 128 + ci * 16);
            cpasync16(dA + so, gA + (size_t)r * D + ci * 8);
            if (!diag) cpasync16(dB + so, gB + (size_t)r * D + ci * 8);
        }
    };

    load_chunk(0, 0);
    CP_COMMIT();

    const uint32_t sBbase = diag ? sA0 : sB0;

    for (int kc = 0; kc < 4; kc++) {
        if (kc < 3) { load_chunk(kc + 1, (kc + 1) & 1); CP_COMMIT(); CP_WAIT(1); }
        else        { CP_WAIT(0); }
        __syncthreads();

        const uint32_t bA = sA0 + (kc & 1) * 16384;
        const uint32_t bB = sBbase + (kc & 1) * 16384;

        #pragma unroll
        for (int ks = 0; ks < 4; ks++) {
            uint32_t a[2][4];
            #pragma unroll
            for (int mf = 0; mf < 2; mf++) {
                int row = wm * 32 + mf * 16 + (sel & 1) * 8 + sub;
                uint32_t off = (uint32_t)(row * 128 + ks * 32 + (sel >> 1) * 16);
                ldsm_x4(a[mf][0], a[mf][1], a[mf][2], a[mf][3], bA + SW128(off));
            }
            uint32_t b[8][2];
            #pragma unroll
            for (int p = 0; p < 4; p++) {
                int n = wn * 64 + p * 16 + (sel >> 1) * 8 + sub;
                uint32_t off = (uint32_t)(n * 128 + ks * 32 + (sel & 1) * 16);
                uint32_t r0, r1, r2, r3;
                ldsm_x4(r0, r1, r2, r3, bB + SW128(off));
                b[2 * p][0] = r0; b[2 * p][1] = r1;
                b[2 * p + 1][0] = r2; b[2 * p + 1][1] = r3;
            }
            #pragma unroll
            for (int mf = 0; mf < 2; mf++)
                #pragma unroll
                for (int nf = 0; nf < 8; nf++)
                    mma16816(c[mf][nf], a[mf][0], a[mf][1], a[mf][2], a[mf][3],
                             b[nf][0], b[nf][1]);
        }
        __syncthreads();
    }

    // ---- epilogue: exp once, accumulate row sums AND column sums ----
    float rs[2][2] = {{0.0f, 0.0f}, {0.0f, 0.0f}};
    float ec[8][2];
    #pragma unroll
    for (int nf = 0; nf < 8; nf++) { ec[nf][0] = 0.0f; ec[nf][1] = 0.0f; }

    #pragma unroll
    for (int mf = 0; mf < 2; mf++) {
        #pragma unroll
        for (int h = 0; h < 2; h++) {
            const int i  = i0 + wm * 32 + mf * 16 + 8 * h + g;
            const int pc = (i + N / 2) & (N - 1);
            #pragma unroll
            for (int nf = 0; nf < 8; nf++) {
                #pragma unroll
                for (int cc = 0; cc < 2; cc++) {
                    const int j = j0 + wn * 64 + nf * 8 + 2 * q + cc;
                    const float v = c[mf][nf][h * 2 + cc];
                    if (j == pc) { g_posdot[i] = v; g_posdot[j] = v; }
                    const float e = (j != i) ? __expf(v * INVT) : 0.0f;
                    rs[mf][h]  += e;
                    ec[nf][cc] += e;
                }
            }
        }
    }

    // row sums: reduce over the 4 q-lanes sharing a row
    #pragma unroll
    for (int mf = 0; mf < 2; mf++) {
        #pragma unroll
        for (int h = 0; h < 2; h++) {
            float v = rs[mf][h];
            v += __shfl_xor_sync(0xffffffffu, v, 1);
            v += __shfl_xor_sync(0xffffffffu, v, 2);
            if (q == 0) {
                const int i = i0 + wm * 32 + mf * 16 + 8 * h + g;
                g_rowpart[(cb * 2 + wn) * N + i] = v;
            }
        }
    }

    // col sums (off-diag tiles only): reduce over the 8 g-lanes sharing a col
    if (!diag) {
        #pragma unroll
        for (int nf = 0; nf < 8; nf++) {
            #pragma unroll
            for (int cc = 0; cc < 2; cc++) {
                float v = ec[nf][cc];
                v += __shfl_xor_sync(0xffffffffu, v, 4);
                v += __shfl_xor_sync(0xffffffffu, v, 8);
                v += __shfl_xor_sync(0xffffffffu, v, 16);
                if (lane < 4) {
                    const int j = j0 + wn * 64 + nf * 8 + 2 * lane + cc;
                    g_colpart[(rb * 4 + wm) * N + j] = v;
                }
            }
        }
    }
}

// ---------------------------------------------------------------------------
// Kernel 3: per-row nll + grid reduction (threadfence pattern, 32 blocks).
// ---------------------------------------------------------------------------
__global__ void finalize_kernel(float* __restrict__ out) {
    const int i = blockIdx.x * 256 + threadIdx.x;
    float s = 0.0f;
    #pragma unroll 8
    for (int sp = 0; sp < 2 * NB; sp++) s += g_rowpart[sp * N + i];
    #pragma unroll 8
    for (int sp = 0; sp < 4 * NB; sp++) s += g_colpart[sp * N + i];
    float local = logf(s) - g_posdot[i] * INVT;

    #pragma unroll
    for (int o = 16; o > 0; o >>= 1) local += __shfl_xor_sync(0xffffffffu, local, o);
    __shared__ float ws[8];
    if ((threadIdx.x & 31) == 0) ws[threadIdx.x >> 5] = local;
    __syncthreads();
    if (threadIdx.x == 0) {
        float v = 0.0f;
        #pragma unroll
        for (int w = 0; w < 8; w++) v += ws[w];
        g_blk[blockIdx.x] = v;
        __threadfence();
        unsigned int tkt = atomicAdd(&g_cnt, 1u);
        if (tkt == 31u) {
            __threadfence();
            float tot = 0.0f;
            #pragma unroll
            for (int k = 0; k < 32; k++) tot += g_blk[k];
            out[0] = tot / (float)N;
            g_cnt = 0u;   // reset for next graph replay
        }
    }
}

// ---------------------------------------------------------------------------
extern "C" void kernel_launch(void* const* d_in, const int* in_sizes, int n_in,
                              void* d_out, int out_size) {
    const float* features = (const float*)d_in[0];
    float* out = (float*)d_out;

    static bool attr_set = false;
    if (!attr_set) {
        cudaFuncSetAttribute(simlse_mma, cudaFuncAttributeMaxDynamicSharedMemorySize,
                             64 * 1024);
        attr_set = true;
    }

    normalize_kernel<<<N / 8, 256>>>(features);
    simlse_mma<<<NTILE, 256, 64 * 1024>>>();
    finalize_kernel<<<32, 256>>>(out);
}

// round 5
// speedup vs baseline: 13.2238x; 1.1919x over previous
#include <cuda_runtime.h>
#include <cuda_bf16.h>
#include <math.h>
#include <stdint.h>

#define N 8192
#define D 256
#define INVT (1.0f / 0.07f)
#define KC 64
#define NB 64                       // 8192/128 blocks per dim
#define NTILE (NB * (NB + 1) / 2)   // 2080 upper-triangular tiles

__device__ __align__(16) __nv_bfloat16 g_fbf16[N * D];  // 4MB normalized bf16
__device__ float g_rowpart[NB * N];   // [cb][i]  2MB
__device__ float g_colpart[NB * N];   // [rb][j]  2MB
__device__ float g_posdot[N];
__device__ float g_blk[32];
__device__ unsigned int g_cnt;

// smem layout: A 2x16KB, B 2x16KB, then reduce buffers
#define SM_ROW  65536                 // float[128][2]  (1KB)
#define SM_COL  (65536 + 1024)        // float[128][4]  (2KB)
#define SMEM_TOTAL (65536 + 1024 + 2048)

// ---------------------------------------------------------------------------
__device__ __forceinline__ uint32_t smem_u32(const void* p) {
    uint32_t a;
    asm("{ .reg .u64 t; cvta.to.shared.u64 t, %1; cvt.u32.u64 %0, t; }" : "=r"(a) : "l"(p));
    return a;
}
#define SW128(o) ((o) ^ (((o) >> 3) & 0x70))

__device__ __forceinline__ void cpasync16(uint32_t s, const void* g) {
    asm volatile("cp.async.cg.shared.global [%0], [%1], 16;" :: "r"(s), "l"(g));
}
#define CP_COMMIT() asm volatile("cp.async.commit_group;" ::: "memory")
#define CP_WAIT(n)  asm volatile("cp.async.wait_group %0;" :: "n"(n) : "memory")

__device__ __forceinline__ void ldsm_x4(uint32_t& r0, uint32_t& r1, uint32_t& r2,
                                        uint32_t& r3, uint32_t a) {
    asm volatile("ldmatrix.sync.aligned.m8n8.x4.shared.b16 {%0,%1,%2,%3}, [%4];"
        : "=r"(r0), "=r"(r1), "=r"(r2), "=r"(r3) : "r"(a));
}
__device__ __forceinline__ void mma16816(float* c, const uint32_t* a,
                                         uint32_t b0, uint32_t b1) {
    asm volatile(
        "mma.sync.aligned.m16n8k16.row.col.f32.bf16.bf16.f32 "
        "{%0,%1,%2,%3},{%4,%5,%6,%7},{%8,%9},{%0,%1,%2,%3};"
        : "+f"(c[0]), "+f"(c[1]), "+f"(c[2]), "+f"(c[3])
        : "r"(a[0]), "r"(a[1]), "r"(a[2]), "r"(a[3]), "r"(b0), "r"(b1));
}

// ---------------------------------------------------------------------------
// Kernel 1: row L2-normalize -> bf16. 2 rows per warp (MLP=4).
// ---------------------------------------------------------------------------
__global__ void normalize_kernel(const float* __restrict__ x) {
    const int warp = threadIdx.x >> 5;
    const int lane = threadIdx.x & 31;
    const int row0 = blockIdx.x * 16 + warp * 2;

    const float* xr0 = x + (size_t)row0 * D + lane * 8;
    const float* xr1 = xr0 + D;
    float4 a0 = *(const float4*)xr0;
    float4 a1 = *(const float4*)(xr0 + 4);
    float4 b0 = *(const float4*)xr1;
    float4 b1 = *(const float4*)(xr1 + 4);

    float s0 = a0.x*a0.x + a0.y*a0.y + a0.z*a0.z + a0.w*a0.w +
               a1.x*a1.x + a1.y*a1.y + a1.z*a1.z + a1.w*a1.w;
    float s1 = b0.x*b0.x + b0.y*b0.y + b0.z*b0.z + b0.w*b0.w +
               b1.x*b1.x + b1.y*b1.y + b1.z*b1.z + b1.w*b1.w;
    #pragma unroll
    for (int o = 16; o > 0; o >>= 1) {
        s0 += __shfl_xor_sync(0xffffffffu, s0, o);
        s1 += __shfl_xor_sync(0xffffffffu, s1, o);
    }
    const float r0 = 1.0f / fmaxf(sqrtf(s0), 1e-8f);
    const float r1 = 1.0f / fmaxf(sqrtf(s1), 1e-8f);

    __nv_bfloat162 p[4];
    p[0] = __floats2bfloat162_rn(a0.x*r0, a0.y*r0);
    p[1] = __floats2bfloat162_rn(a0.z*r0, a0.w*r0);
    p[2] = __floats2bfloat162_rn(a1.x*r0, a1.y*r0);
    p[3] = __floats2bfloat162_rn(a1.z*r0, a1.w*r0);
    *(uint4*)(g_fbf16 + (size_t)row0 * D + lane * 8) = *(uint4*)p;
    p[0] = __floats2bfloat162_rn(b0.x*r1, b0.y*r1);
    p[1] = __floats2bfloat162_rn(b0.z*r1, b0.w*r1);
    p[2] = __floats2bfloat162_rn(b1.x*r1, b1.y*r1);
    p[3] = __floats2bfloat162_rn(b1.z*r1, b1.w*r1);
    *(uint4*)(g_fbf16 + (size_t)(row0 + 1) * D + lane * 8) = *(uint4*)p;
}

// ---------------------------------------------------------------------------
// Kernel 2: HMMA fused sim GEMM, upper-triangular tiles, epilogue interleaved
// into the last K-chunk; in-smem reduction of row/col partials.
// ---------------------------------------------------------------------------
__global__ __launch_bounds__(256, 2) void simlse_mma() {
    extern __shared__ __align__(1024) char smem[];
    const uint32_t sA0 = smem_u32(smem);
    const uint32_t sB0 = sA0 + 2 * 16384;
    float* sm_row = (float*)(smem + SM_ROW);   // [128][2]
    float* sm_col = (float*)(smem + SM_COL);   // [128][4]

    // triangular tile map
    int t = blockIdx.x, rb = 0, base = 0;
    while (base + (NB - rb) <= t) { base += NB - rb; rb++; }
    const int cb = rb + (t - base);
    const bool diag = (rb == cb);

    const int tid  = threadIdx.x;
    const int wid  = tid >> 5;
    const int lane = tid & 31;
    const int wm   = wid >> 1;
    const int wn   = wid & 1;
    const int i0   = rb * 128;
    const int j0   = cb * 128;

    const int sel = lane >> 3;
    const int sub = lane & 7;
    const int g   = lane >> 2;
    const int q   = lane & 3;

    float c[2][8][4];
    #pragma unroll
    for (int mf = 0; mf < 2; mf++)
        #pragma unroll
        for (int nf = 0; nf < 8; nf++)
            #pragma unroll
            for (int e = 0; e < 4; e++) c[mf][nf][e] = 0.0f;

    auto load_chunk = [&](int kc, int bf) {
        const __nv_bfloat16* gA = g_fbf16 + (size_t)i0 * D + kc * KC;
        const __nv_bfloat16* gB = g_fbf16 + (size_t)j0 * D + kc * KC;
        const uint32_t dA = sA0 + bf * 16384;
        const uint32_t dB = sB0 + bf * 16384;
        #pragma unroll
        for (int v = 0; v < 4; v++) {
            int idx = tid + 256 * v;
            int r   = idx >> 3;
            int ci  = idx & 7;
            uint32_t so = SW128(r * 128 + ci * 16);
            cpasync16(dA + so, gA + (size_t)r * D + ci * 8);
            if (!diag) cpasync16(dB + so, gB + (size_t)r * D + ci * 8);
        }
    };

    load_chunk(0, 0);
    CP_COMMIT();

    const uint32_t sBbase = diag ? sA0 : sB0;

    float rs[2][2] = {{0.0f, 0.0f}, {0.0f, 0.0f}};

    // A-fragment loader for one ks
    auto load_a = [&](uint32_t bA, int ks, uint32_t a[2][4]) {
        #pragma unroll
        for (int mf = 0; mf < 2; mf++) {
            int row = wm * 32 + mf * 16 + (sel & 1) * 8 + sub;
            uint32_t off = (uint32_t)(row * 128 + ks * 32 + (sel >> 1) * 16);
            ldsm_x4(a[mf][0], a[mf][1], a[mf][2], a[mf][3], bA + SW128(off));
        }
    };

    for (int kc = 0; kc < 3; kc++) {
        load_chunk(kc + 1, (kc + 1) & 1);
        CP_COMMIT();
        CP_WAIT(1);
        __syncthreads();

        const uint32_t bA = sA0 + (kc & 1) * 16384;
        const uint32_t bB = sBbase + (kc & 1) * 16384;

        #pragma unroll
        for (int ks = 0; ks < 4; ks++) {
            uint32_t a[2][4];
            load_a(bA, ks, a);
            #pragma unroll
            for (int p = 0; p < 4; p++) {
                int n = wn * 64 + p * 16 + (sel >> 1) * 8 + sub;
                uint32_t off = (uint32_t)(n * 128 + ks * 32 + (sel & 1) * 16);
                uint32_t r0, r1, r2, r3;
                ldsm_x4(r0, r1, r2, r3, bB + SW128(off));
                #pragma unroll
                for (int mf = 0; mf < 2; mf++) {
                    mma16816(c[mf][2 * p],     a[mf], r0, r1);
                    mma16816(c[mf][2 * p + 1], a[mf], r2, r3);
                }
            }
        }
        __syncthreads();
    }

    // ---- last chunk (kc=3): ks 0-2 normal, ks 3 interleaved with epilogue ----
    CP_WAIT(0);
    __syncthreads();
    {
        const uint32_t bA = sA0 + 16384;
        const uint32_t bB = sBbase + 16384;

        #pragma unroll
        for (int ks = 0; ks < 3; ks++) {
            uint32_t a[2][4];
            load_a(bA, ks, a);
            #pragma unroll
            for (int p = 0; p < 4; p++) {
                int n = wn * 64 + p * 16 + (sel >> 1) * 8 + sub;
                uint32_t off = (uint32_t)(n * 128 + ks * 32 + (sel & 1) * 16);
                uint32_t r0, r1, r2, r3;
                ldsm_x4(r0, r1, r2, r3, bB + SW128(off));
                #pragma unroll
                for (int mf = 0; mf < 2; mf++) {
                    mma16816(c[mf][2 * p],     a[mf], r0, r1);
                    mma16816(c[mf][2 * p + 1], a[mf], r2, r3);
                }
            }
        }

        // ks == 3: per nf, finish MMA then immediately run that nf's epilogue.
        uint32_t a[2][4];
        load_a(bA, 3, a);
        #pragma unroll
        for (int p = 0; p < 4; p++) {
            int n = wn * 64 + p * 16 + (sel >> 1) * 8 + sub;
            uint32_t off = (uint32_t)(n * 128 + 3 * 32 + (sel & 1) * 16);
            uint32_t r0, r1, r2, r3;
            ldsm_x4(r0, r1, r2, r3, bB + SW128(off));
            #pragma unroll
            for (int half = 0; half < 2; half++) {
                const int nf = 2 * p + half;
                mma16816(c[0][nf], a[0], half ? r2 : r0, half ? r3 : r1);
                mma16816(c[1][nf], a[1], half ? r2 : r0, half ? r3 : r1);

                // epilogue for this nf: 8 exps, row adds, col partials
                float s0 = 0.0f, s1 = 0.0f;
                const int jb = j0 + wn * 64 + nf * 8 + 2 * q;
                #pragma unroll
                for (int mf = 0; mf < 2; mf++) {
                    #pragma unroll
                    for (int h = 0; h < 2; h++) {
                        const int i  = i0 + wm * 32 + mf * 16 + 8 * h + g;
                        const int pc = (i + N / 2) & (N - 1);
                        const float v0 = c[mf][nf][h * 2 + 0];
                        const float v1 = c[mf][nf][h * 2 + 1];
                        if (jb == pc)     { g_posdot[i] = v0; g_posdot[jb] = v0; }
                        if (jb + 1 == pc) { g_posdot[i] = v1; g_posdot[jb + 1] = v1; }
                        const float e0 = (jb != i)     ? __expf(v0 * INVT) : 0.0f;
                        const float e1 = (jb + 1 != i) ? __expf(v1 * INVT) : 0.0f;
                        rs[mf][h] += e0 + e1;
                        s0 += e0;
                        s1 += e1;
                    }
                }
                // reduce col partials over the 8 g-lanes
                s0 += __shfl_xor_sync(0xffffffffu, s0, 4);
                s0 += __shfl_xor_sync(0xffffffffu, s0, 8);
                s0 += __shfl_xor_sync(0xffffffffu, s0, 16);
                s1 += __shfl_xor_sync(0xffffffffu, s1, 4);
                s1 += __shfl_xor_sync(0xffffffffu, s1, 8);
                s1 += __shfl_xor_sync(0xffffffffu, s1, 16);
                if (g == nf) {
                    const int jl = wn * 64 + nf * 8 + 2 * q;
                    sm_col[jl * 4 + wm]       = s0;
                    sm_col[(jl + 1) * 4 + wm] = s1;
                }
            }
        }
    }

    // row partials: reduce over the 4 q-lanes, stash to smem
    #pragma unroll
    for (int mf = 0; mf < 2; mf++) {
        #pragma unroll
        for (int h = 0; h < 2; h++) {
            float v = rs[mf][h];
            v += __shfl_xor_sync(0xffffffffu, v, 1);
            v += __shfl_xor_sync(0xffffffffu, v, 2);
            if (q == 0) {
                const int il = wm * 32 + mf * 16 + 8 * h + g;
                sm_row[il * 2 + wn] = v;
            }
        }
    }
    __syncthreads();

    if (tid < 128) {
        g_rowpart[(size_t)cb * N + i0 + tid] = sm_row[tid * 2] + sm_row[tid * 2 + 1];
    } else if (!diag) {
        const int j = tid - 128;
        g_colpart[(size_t)rb * N + j0 + j] =
            sm_col[j * 4] + sm_col[j * 4 + 1] + sm_col[j * 4 + 2] + sm_col[j * 4 + 3];
    }
}

// ---------------------------------------------------------------------------
// Kernel 3: per-row nll + grid reduction (threadfence pattern, 32 blocks).
// ---------------------------------------------------------------------------
__global__ void finalize_kernel(float* __restrict__ out) {
    const int i = blockIdx.x * 256 + threadIdx.x;
    float s = 0.0f;
    #pragma unroll 8
    for (int sp = 0; sp < NB; sp++) s += g_rowpart[(size_t)sp * N + i];
    #pragma unroll 8
    for (int sp = 0; sp < NB; sp++) s += g_colpart[(size_t)sp * N + i];
    float local = logf(s) - g_posdot[i] * INVT;

    #pragma unroll
    for (int o = 16; o > 0; o >>= 1) local += __shfl_xor_sync(0xffffffffu, local, o);
    __shared__ float ws[8];
    if ((threadIdx.x & 31) == 0) ws[threadIdx.x >> 5] = local;
    __syncthreads();
    if (threadIdx.x == 0) {
        float v = 0.0f;
        #pragma unroll
        for (int w = 0; w < 8; w++) v += ws[w];
        g_blk[blockIdx.x] = v;
        __threadfence();
        unsigned int tkt = atomicAdd(&g_cnt, 1u);
        if (tkt == 31u) {
            __threadfence();
            float tot = 0.0f;
            #pragma unroll
            for (int k = 0; k < 32; k++) tot += g_blk[k];
            out[0] = tot / (float)N;
            g_cnt = 0u;   // reset for next graph replay
        }
    }
}

// ---------------------------------------------------------------------------
extern "C" void kernel_launch(void* const* d_in, const int* in_sizes, int n_in,
                              void* d_out, int out_size) {
    const float* features = (const float*)d_in[0];
    float* out = (float*)d_out;

    static bool attr_set = false;
    if (!attr_set) {
        cudaFuncSetAttribute(simlse_mma, cudaFuncAttributeMaxDynamicSharedMemorySize,
                             SMEM_TOTAL);
        attr_set = true;
    }

    normalize_kernel<<<N / 16, 256>>>(features);
    simlse_mma<<<NTILE, 256, SMEM_TOTAL>>>();
    finalize_kernel<<<32, 256>>>(out);
}

// round 6
// speedup vs baseline: 13.7037x; 1.0363x over previous
#include <cuda_runtime.h>
#include <cuda_bf16.h>
#include <math.h>
#include <stdint.h>

#define N 8192
#define D 256
#define INVT (1.0f / 0.07f)
#define KC 64
#define NB 64                       // 8192/128 blocks per dim
#define NTILE (NB * (NB + 1) / 2)   // 2080 upper-triangular tiles

__device__ __align__(16) __nv_bfloat16 g_fbf16[N * D];  // 4MB normalized bf16
__device__ float g_rowpart[NB * N];   // [cb][i]  2MB
__device__ float g_colpart[NB * N];   // [rb][j]  2MB
__device__ float g_posdot[N];
__device__ float g_blk[128];
__device__ unsigned int g_cnt;

// smem layout: A 2x16KB, B 2x16KB, then reduce buffers
#define SM_ROW  65536                 // float[128][2]  (1KB)
#define SM_COL  (65536 + 1024)        // float[128][4]  (2KB)
#define SMEM_TOTAL (65536 + 1024 + 2048)

// ---------------------------------------------------------------------------
__device__ __forceinline__ uint32_t smem_u32(const void* p) {
    uint32_t a;
    asm("{ .reg .u64 t; cvta.to.shared.u64 t, %1; cvt.u32.u64 %0, t; }" : "=r"(a) : "l"(p));
    return a;
}
#define SW128(o) ((o) ^ (((o) >> 3) & 0x70))

__device__ __forceinline__ void cpasync16(uint32_t s, const void* g) {
    asm volatile("cp.async.cg.shared.global [%0], [%1], 16;" :: "r"(s), "l"(g));
}
#define CP_COMMIT() asm volatile("cp.async.commit_group;" ::: "memory")
#define CP_WAIT(n)  asm volatile("cp.async.wait_group %0;" :: "n"(n) : "memory")

__device__ __forceinline__ void ldsm_x4(uint32_t& r0, uint32_t& r1, uint32_t& r2,
                                        uint32_t& r3, uint32_t a) {
    asm volatile("ldmatrix.sync.aligned.m8n8.x4.shared.b16 {%0,%1,%2,%3}, [%4];"
        : "=r"(r0), "=r"(r1), "=r"(r2), "=r"(r3) : "r"(a));
}
__device__ __forceinline__ void mma16816(float* c, const uint32_t* a,
                                         uint32_t b0, uint32_t b1) {
    asm volatile(
        "mma.sync.aligned.m16n8k16.row.col.f32.bf16.bf16.f32 "
        "{%0,%1,%2,%3},{%4,%5,%6,%7},{%8,%9},{%0,%1,%2,%3};"
        : "+f"(c[0]), "+f"(c[1]), "+f"(c[2]), "+f"(c[3])
        : "r"(a[0]), "r"(a[1]), "r"(a[2]), "r"(a[3]), "r"(b0), "r"(b1));
}

// ---------------------------------------------------------------------------
// Kernel 1: row L2-normalize -> bf16. 2 rows per warp, 128-thread blocks.
// ---------------------------------------------------------------------------
__global__ void normalize_kernel(const float* __restrict__ x) {
    const int warp = threadIdx.x >> 5;
    const int lane = threadIdx.x & 31;
    const int row0 = blockIdx.x * 8 + warp * 2;

    const float* xr0 = x + (size_t)row0 * D + lane * 8;
    const float* xr1 = xr0 + D;
    float4 a0 = *(const float4*)xr0;
    float4 a1 = *(const float4*)(xr0 + 4);
    float4 b0 = *(const float4*)xr1;
    float4 b1 = *(const float4*)(xr1 + 4);

    float s0 = a0.x*a0.x + a0.y*a0.y + a0.z*a0.z + a0.w*a0.w +
               a1.x*a1.x + a1.y*a1.y + a1.z*a1.z + a1.w*a1.w;
    float s1 = b0.x*b0.x + b0.y*b0.y + b0.z*b0.z + b0.w*b0.w +
               b1.x*b1.x + b1.y*b1.y + b1.z*b1.z + b1.w*b1.w;
    #pragma unroll
    for (int o = 16; o > 0; o >>= 1) {
        s0 += __shfl_xor_sync(0xffffffffu, s0, o);
        s1 += __shfl_xor_sync(0xffffffffu, s1, o);
    }
    const float r0 = 1.0f / fmaxf(sqrtf(s0), 1e-8f);
    const float r1 = 1.0f / fmaxf(sqrtf(s1), 1e-8f);

    __nv_bfloat162 p[4];
    p[0] = __floats2bfloat162_rn(a0.x*r0, a0.y*r0);
    p[1] = __floats2bfloat162_rn(a0.z*r0, a0.w*r0);
    p[2] = __floats2bfloat162_rn(a1.x*r0, a1.y*r0);
    p[3] = __floats2bfloat162_rn(a1.z*r0, a1.w*r0);
    *(uint4*)(g_fbf16 + (size_t)row0 * D + lane * 8) = *(uint4*)p;
    p[0] = __floats2bfloat162_rn(b0.x*r1, b0.y*r1);
    p[1] = __floats2bfloat162_rn(b0.z*r1, b0.w*r1);
    p[2] = __floats2bfloat162_rn(b1.x*r1, b1.y*r1);
    p[3] = __floats2bfloat162_rn(b1.z*r1, b1.w*r1);
    *(uint4*)(g_fbf16 + (size_t)(row0 + 1) * D + lane * 8) = *(uint4*)p;
}

// ---------------------------------------------------------------------------
// Kernel 2: HMMA fused sim GEMM, upper-triangular tiles, 1 barrier per
// K-chunk, B-fragments prefetched ahead of MMAs, epilogue interleaved into
// the last ks-step; in-smem reduction of row/col partials.
// ---------------------------------------------------------------------------
__global__ __launch_bounds__(256, 2) void simlse_mma() {
    extern __shared__ __align__(1024) char smem[];
    const uint32_t sA0 = smem_u32(smem);
    const uint32_t sB0 = sA0 + 2 * 16384;
    float* sm_row = (float*)(smem + SM_ROW);   // [128][2]
    float* sm_col = (float*)(smem + SM_COL);   // [128][4]

    // triangular tile map
    int t = blockIdx.x, rb = 0, base = 0;
    while (base + (NB - rb) <= t) { base += NB - rb; rb++; }
    const int cb = rb + (t - base);
    const bool diag = (rb == cb);

    const int tid  = threadIdx.x;
    const int lane = tid & 31;
    const int wm   = (tid >> 5) >> 1;
    const int wn   = (tid >> 5) & 1;
    const int i0   = rb * 128;
    const int j0   = cb * 128;

    const int sel = lane >> 3;
    const int sub = lane & 7;
    const int g   = lane >> 2;
    const int q   = lane & 3;

    float c[2][8][4];
    #pragma unroll
    for (int mf = 0; mf < 2; mf++)
        #pragma unroll
        for (int nf = 0; nf < 8; nf++)
            #pragma unroll
            for (int e = 0; e < 4; e++) c[mf][nf][e] = 0.0f;

    auto load_chunk = [&](int kc, int bf) {
        const __nv_bfloat16* gA = g_fbf16 + (size_t)i0 * D + kc * KC;
        const __nv_bfloat16* gB = g_fbf16 + (size_t)j0 * D + kc * KC;
        const uint32_t dA = sA0 + bf * 16384;
        const uint32_t dB = sB0 + bf * 16384;
        #pragma unroll
        for (int v = 0; v < 4; v++) {
            int idx = tid + 256 * v;
            int r   = idx >> 3;
            int ci  = idx & 7;
            uint32_t so = SW128(r * 128 + ci * 16);
            cpasync16(dA + so, gA + (size_t)r * D + ci * 8);
            if (!diag) cpasync16(dB + so, gB + (size_t)r * D + ci * 8);
        }
    };

    load_chunk(0, 0);
    CP_COMMIT();

    const uint32_t sBbase = diag ? sA0 : sB0;

    float rs[2][2] = {{0.0f, 0.0f}, {0.0f, 0.0f}};

    auto load_a = [&](uint32_t bA, int ks, uint32_t a[2][4]) {
        #pragma unroll
        for (int mf = 0; mf < 2; mf++) {
            int row = wm * 32 + mf * 16 + (sel & 1) * 8 + sub;
            uint32_t off = (uint32_t)(row * 128 + ks * 32 + (sel >> 1) * 16);
            ldsm_x4(a[mf][0], a[mf][1], a[mf][2], a[mf][3], bA + SW128(off));
        }
    };
    auto load_b = [&](uint32_t bB, int ks, uint32_t b[4][4]) {
        #pragma unroll
        for (int p = 0; p < 4; p++) {
            int n = wn * 64 + p * 16 + (sel >> 1) * 8 + sub;
            uint32_t off = (uint32_t)(n * 128 + ks * 32 + (sel & 1) * 16);
            ldsm_x4(b[p][0], b[p][1], b[p][2], b[p][3], bB + SW128(off));
        }
    };

    // kc = 0..2: single barrier per chunk, loads issued after the barrier.
    for (int kc = 0; kc < 3; kc++) {
        CP_WAIT(0);
        __syncthreads();
        load_chunk(kc + 1, (kc + 1) & 1);
        CP_COMMIT();

        const uint32_t bA = sA0 + (kc & 1) * 16384;
        const uint32_t bB = sBbase + (kc & 1) * 16384;

        #pragma unroll
        for (int ks = 0; ks < 4; ks++) {
            uint32_t a[2][4], b[4][4];
            load_a(bA, ks, a);
            load_b(bB, ks, b);
            #pragma unroll
            for (int p = 0; p < 4; p++)
                #pragma unroll
                for (int mf = 0; mf < 2; mf++) {
                    mma16816(c[mf][2 * p],     a[mf], b[p][0], b[p][1]);
                    mma16816(c[mf][2 * p + 1], a[mf], b[p][2], b[p][3]);
                }
        }
    }

    // ---- last chunk (kc=3): ks 0-2 normal, ks 3 interleaved with epilogue ----
    CP_WAIT(0);
    __syncthreads();
    {
        const uint32_t bA = sA0 + 16384;
        const uint32_t bB = sBbase + 16384;

        #pragma unroll
        for (int ks = 0; ks < 3; ks++) {
            uint32_t a[2][4], b[4][4];
            load_a(bA, ks, a);
            load_b(bB, ks, b);
            #pragma unroll
            for (int p = 0; p < 4; p++)
                #pragma unroll
                for (int mf = 0; mf < 2; mf++) {
                    mma16816(c[mf][2 * p],     a[mf], b[p][0], b[p][1]);
                    mma16816(c[mf][2 * p + 1], a[mf], b[p][2], b[p][3]);
                }
        }

        // ks == 3: per nf, finish MMA then immediately run that nf's epilogue.
        uint32_t a[2][4], b[4][4];
        load_a(bA, 3, a);
        load_b(bB, 3, b);
        #pragma unroll
        for (int p = 0; p < 4; p++) {
            #pragma unroll
            for (int half = 0; half < 2; half++) {
                const int nf = 2 * p + half;
                mma16816(c[0][nf], a[0], b[p][2 * half], b[p][2 * half + 1]);
                mma16816(c[1][nf], a[1], b[p][2 * half], b[p][2 * half + 1]);

                // epilogue for this nf: 8 exps, row adds, col partials
                float s0 = 0.0f, s1 = 0.0f;
                const int jb = j0 + wn * 64 + nf * 8 + 2 * q;
                #pragma unroll
                for (int mf = 0; mf < 2; mf++) {
                    #pragma unroll
                    for (int h = 0; h < 2; h++) {
                        const int i  = i0 + wm * 32 + mf * 16 + 8 * h + g;
                        const int pc = (i + N / 2) & (N - 1);
                        const float v0 = c[mf][nf][h * 2 + 0];
                        const float v1 = c[mf][nf][h * 2 + 1];
                        if (jb == pc)     { g_posdot[i] = v0; g_posdot[jb] = v0; }
                        if (jb + 1 == pc) { g_posdot[i] = v1; g_posdot[jb + 1] = v1; }
                        const float e0 = (jb != i)     ? __expf(v0 * INVT) : 0.0f;
                        const float e1 = (jb + 1 != i) ? __expf(v1 * INVT) : 0.0f;
                        rs[mf][h] += e0 + e1;
                        s0 += e0;
                        s1 += e1;
                    }
                }
                // reduce col partials over the 8 g-lanes
                s0 += __shfl_xor_sync(0xffffffffu, s0, 4);
                s0 += __shfl_xor_sync(0xffffffffu, s0, 8);
                s0 += __shfl_xor_sync(0xffffffffu, s0, 16);
                s1 += __shfl_xor_sync(0xffffffffu, s1, 4);
                s1 += __shfl_xor_sync(0xffffffffu, s1, 8);
                s1 += __shfl_xor_sync(0xffffffffu, s1, 16);
                if (g == nf) {
                    const int jl = wn * 64 + nf * 8 + 2 * q;
                    sm_col[jl * 4 + wm]       = s0;
                    sm_col[(jl + 1) * 4 + wm] = s1;
                }
            }
        }
    }

    // row partials: reduce over the 4 q-lanes, stash to smem
    #pragma unroll
    for (int mf = 0; mf < 2; mf++) {
        #pragma unroll
        for (int h = 0; h < 2; h++) {
            float v = rs[mf][h];
            v += __shfl_xor_sync(0xffffffffu, v, 1);
            v += __shfl_xor_sync(0xffffffffu, v, 2);
            if (q == 0) {
                const int il = wm * 32 + mf * 16 + 8 * h + g;
                sm_row[il * 2 + wn] = v;
            }
        }
    }
    __syncthreads();

    if (tid < 128) {
        g_rowpart[(size_t)cb * N + i0 + tid] = sm_row[tid * 2] + sm_row[tid * 2 + 1];
    } else if (!diag) {
        const int j = tid - 128;
        g_colpart[(size_t)rb * N + j0 + j] =
            sm_col[j * 4] + sm_col[j * 4 + 1] + sm_col[j * 4 + 2] + sm_col[j * 4 + 3];
    }
}

// ---------------------------------------------------------------------------
// Kernel 3: per-row nll. 128 blocks x 256 threads, 4 threads per row.
// ---------------------------------------------------------------------------
__global__ void finalize_kernel(float* __restrict__ out) {
    const int tid  = threadIdx.x;
    const int part = tid & 3;                      // 0..3
    const int i    = blockIdx.x * 64 + (tid >> 2); // row

    const float* basep = (part < 2) ? g_rowpart : g_colpart;
    const int off = (part & 1) * 32;

    float s = 0.0f;
    #pragma unroll 8
    for (int k = 0; k < 32; k++) s += basep[(size_t)(off + k) * N + i];

    // combine the 4 parts of this row (consecutive lanes)
    s += __shfl_xor_sync(0xffffffffu, s, 1);
    s += __shfl_xor_sync(0xffffffffu, s, 2);

    float local = (part == 0) ? (logf(s) - g_posdot[i] * INVT) : 0.0f;
    #pragma unroll
    for (int o = 16; o > 0; o >>= 1) local += __shfl_xor_sync(0xffffffffu, local, o);

    __shared__ float ws[8];
    if ((tid & 31) == 0) ws[tid >> 5] = local;
    __syncthreads();
    if (tid == 0) {
        float v = 0.0f;
        #pragma unroll
        for (int w = 0; w < 8; w++) v += ws[w];
        g_blk[blockIdx.x] = v;
        __threadfence();
        unsigned int tkt = atomicAdd(&g_cnt, 1u);
        if (tkt == 127u) {
            __threadfence();
            float tot = 0.0f;
            #pragma unroll 16
            for (int k = 0; k < 128; k++) tot += g_blk[k];
            out[0] = tot / (float)N;
            g_cnt = 0u;   // reset for next graph replay
        }
    }
}

// ---------------------------------------------------------------------------
extern "C" void kernel_launch(void* const* d_in, const int* in_sizes, int n_in,
                              void* d_out, int out_size) {
    const float* features = (const float*)d_in[0];
    float* out = (float*)d_out;

    static bool attr_set = false;
    if (!attr_set) {
        cudaFuncSetAttribute(simlse_mma, cudaFuncAttributeMaxDynamicSharedMemorySize,
                             SMEM_TOTAL);
        attr_set = true;
    }

    normalize_kernel<<<N / 8, 128>>>(features);
    simlse_mma<<<NTILE, 256, SMEM_TOTAL>>>();
    finalize_kernel<<<128, 256>>>(out);
}